// round 4
// baseline (speedup 1.0000x reference)
#include <cuda_runtime.h>
#include <cstdint>
#include <cstddef>

#define NTHR 256
#define TILE 32
#define KC 32
#define ALD 260
#define WT2LD 520
#define HDIM 256

__device__ float g_zk[8192 * 128];

union F2U { float2 f; unsigned long long u; };

__device__ __forceinline__ float2 ffma2(float2 a, float2 b, float2 c) {
    F2U A, Bv, C; A.f = a; Bv.f = b; C.f = c;
    asm("fma.rn.f32x2 %0, %1, %2, %0;" : "+l"(C.u) : "l"(A.u), "l"(Bv.u));
    return C.f;
}

template<bool FINAL, int G>
__device__ __forceinline__ void run_layer(
    const float* __restrict__ sIn, float* __restrict__ sOut, float* __restrict__ wt2,
    const float* __restrict__ W, const float* __restrict__ bias,
    int in_dim, int in_p, int out_dim,
    float* __restrict__ gOut, int out_ld, int out_off, int row0, int tid)
{
    const int tx = tid & 31;
    const int ty = tid >> 5;
    const int r0 = ty * 4;

    float2 acc[4][2 * G];
    #pragma unroll
    for (int i = 0; i < 4; ++i)
        #pragma unroll
        for (int j = 0; j < 2 * G; ++j) acc[i][j] = make_float2(0.f, 0.f);

    for (int k0 = 0; k0 < in_p; k0 += KC) {
        const int kc = min(KC, in_p - k0);
        const int cnt = out_dim * kc;
        for (int i = tid; i < cnt; i += NTHR) {
            int c  = i % out_dim;
            int kk = i / out_dim;
            int kg = k0 + kk;
            float w = (kg < in_dim) ? W[c * in_dim + kg] : 0.f;
            wt2[(kk >> 1) * WT2LD + 2 * c + (kk & 1)] = w;
        }
        __syncthreads();

        const int kpe = kc >> 1;
        #pragma unroll 4
        for (int kp = 0; kp < kpe; ++kp) {
            const float* abase = sIn + k0 + 2 * kp;
            float2 a[4];
            a[0] = *(const float2*)(abase + (r0 + 0) * ALD);
            a[1] = *(const float2*)(abase + (r0 + 1) * ALD);
            a[2] = *(const float2*)(abase + (r0 + 2) * ALD);
            a[3] = *(const float2*)(abase + (r0 + 3) * ALD);
            const float* wr = wt2 + kp * WT2LD + 4 * tx;
            float2 b[2 * G];
            #pragma unroll
            for (int g = 0; g < G; ++g) {
                float4 q = *(const float4*)(wr + 128 * g);
                b[2 * g]     = make_float2(q.x, q.y);
                b[2 * g + 1] = make_float2(q.z, q.w);
            }
            #pragma unroll
            for (int i = 0; i < 4; ++i)
                #pragma unroll
                for (int j = 0; j < 2 * G; ++j)
                    acc[i][j] = ffma2(a[i], b[j], acc[i][j]);
        }
        __syncthreads();
    }

    if constexpr (FINAL) {
        #pragma unroll
        for (int g = 0; g < G; ++g) {
            #pragma unroll
            for (int h = 0; h < 2; ++h) {
                int c = 64 * g + 2 * tx + h;
                if (c < out_dim) {
                    float bv = bias[c];
                    #pragma unroll
                    for (int i = 0; i < 4; ++i) {
                        float v = acc[i][2 * g + h].x + acc[i][2 * g + h].y + bv;
                        gOut[(size_t)(row0 + r0 + i) * out_ld + out_off + c] = v;
                    }
                }
            }
        }
    } else {
        #pragma unroll
        for (int g = 0; g < G; ++g) {
            int c0 = 64 * g + 2 * tx;
            float2 bv = *(const float2*)&bias[c0];
            #pragma unroll
            for (int i = 0; i < 4; ++i) {
                float2 v;
                v.x = fmaxf(acc[i][2 * g].x     + acc[i][2 * g].y     + bv.x, 0.f);
                v.y = fmaxf(acc[i][2 * g + 1].x + acc[i][2 * g + 1].y + bv.y, 0.f);
                *(float2*)&sOut[(r0 + i) * ALD + c0] = v;
            }
        }
    }
    __syncthreads();
}

__global__ void __launch_bounds__(NTHR, 2) mlp3_kernel(
    const float* __restrict__ in, int in_ld, int in_off, int in_dim,
    const float* __restrict__ W0, const float* __restrict__ b0,
    const float* __restrict__ W1, const float* __restrict__ b1,
    const float* __restrict__ W2, const float* __restrict__ b2,
    int out_dim, float* __restrict__ gOut, int out_ld, int out_off)
{
    extern __shared__ float smem[];
    float* actA = smem;
    float* actB = actA + TILE * ALD;
    float* wt2  = actB + TILE * ALD;

    const int tid  = threadIdx.x;
    const int row0 = blockIdx.x * TILE;
    const int in_p = (in_dim + 1) & ~1;

    for (int i = tid; i < TILE * in_p; i += NTHR) {
        int r = i / in_p, k = i % in_p;
        actA[r * ALD + k] =
            (k < in_dim) ? in[(size_t)(row0 + r) * in_ld + in_off + k] : 0.f;
    }
    __syncthreads();

    run_layer<false, 4>(actA, actB, wt2, W0, b0, in_dim, in_p, HDIM,
                        nullptr, 0, 0, row0, tid);
    run_layer<false, 4>(actB, actA, wt2, W1, b1, HDIM, HDIM, HDIM,
                        nullptr, 0, 0, row0, tid);
    if (out_dim <= 64)
        run_layer<true, 1>(actA, nullptr, wt2, W2, b2, HDIM, HDIM, out_dim,
                           gOut, out_ld, out_off, row0, tid);
    else
        run_layer<true, 2>(actA, nullptr, wt2, W2, b2, HDIM, HDIM, out_dim,
                           gOut, out_ld, out_off, row0, tid);
}

__global__ void __launch_bounds__(NTHR, 2) koopman_kernel(
    const float* __restrict__ zk, const float* __restrict__ u,
    const float* __restrict__ A, const float* __restrict__ Bw,
    float* __restrict__ zpred)
{
    extern __shared__ float smem[];
    float* As = smem;            // 128*128 transposed A
    float* z0 = As + 16384;      // 32*132
    float* z1 = z0 + 4224;
    float* bw = z1 + 4224;       // 4*128 transposed B
    float* us = bw + 512;        // 32*4

    const int tid  = threadIdx.x;
    const int row0 = blockIdx.x * 32;

    for (int i = tid; i < 16384; i += NTHR) {
        int o = i & 127, k = i >> 7;
        As[k * 128 + o] = A[o * 128 + k];
    }
    for (int i = tid; i < 512; i += NTHR) {
        int o = i & 127, j = i >> 7;
        bw[j * 128 + o] = Bw[o * 4 + j];
    }
    for (int i = tid; i < 4096; i += NTHR) {
        int r = i >> 7, k = i & 127;
        z0[r * 132 + k] = zk[(size_t)(row0 + r) * 128 + k];
    }
    const int oc = (tid & 63) * 2;
    const int rg = tid >> 6;
    __syncthreads();

    for (int s = 0; s < 64; ++s) {
        if (tid < 128) {
            int r = tid >> 2, j = tid & 3;
            us[r * 4 + j] = u[((size_t)(row0 + r) * 64 + s) * 4 + j];
        }
        __syncthreads();
        const float* zc = (s & 1) ? z1 : z0;
        float*       zn = (s & 1) ? z0 : z1;

        float2 acc[8];
        #pragma unroll
        for (int r = 0; r < 8; ++r) acc[r] = make_float2(0.f, 0.f);

        #pragma unroll
        for (int j = 0; j < 4; ++j) {
            float2 bv = *(const float2*)&bw[j * 128 + oc];
            #pragma unroll
            for (int r = 0; r < 8; ++r) {
                float uv = us[(rg * 8 + r) * 4 + j];
                acc[r] = ffma2(bv, make_float2(uv, uv), acc[r]);
            }
        }
        for (int k = 0; k < 128; ++k) {
            float2 av = *(const float2*)&As[k * 128 + oc];
            #pragma unroll
            for (int r = 0; r < 8; ++r) {
                float zv = zc[(rg * 8 + r) * 132 + k];
                acc[r] = ffma2(av, make_float2(zv, zv), acc[r]);
            }
        }
        #pragma unroll
        for (int r = 0; r < 8; ++r) {
            int rr = rg * 8 + r;
            *(float2*)&zn[rr * 132 + oc] = acc[r];
            *(float2*)&zpred[(((size_t)(row0 + rr)) * 64 + s) * 128 + oc] = acc[r];
        }
        __syncthreads();
    }
}

extern "C" void kernel_launch(void* const* d_in, const int* in_sizes, int n_in,
                              void* d_out, int out_size) {
    (void)in_sizes; (void)n_in; (void)out_size;
    const float* x_k   = (const float*)d_in[0];
    const float* u_seq = (const float*)d_in[1];
    const float* xnext = (const float*)d_in[2];
    const float* ep_w0 = (const float*)d_in[3];
    const float* ep_b0 = (const float*)d_in[4];
    const float* ep_w1 = (const float*)d_in[5];
    const float* ep_b1 = (const float*)d_in[6];
    const float* ep_w2 = (const float*)d_in[7];
    const float* ep_b2 = (const float*)d_in[8];
    const float* er_w0 = (const float*)d_in[9];
    const float* er_b0 = (const float*)d_in[10];
    const float* er_w1 = (const float*)d_in[11];
    const float* er_b1 = (const float*)d_in[12];
    const float* er_w2 = (const float*)d_in[13];
    const float* er_b2 = (const float*)d_in[14];
    const float* dp_w0 = (const float*)d_in[15];
    const float* dp_b0 = (const float*)d_in[16];
    const float* dp_w1 = (const float*)d_in[17];
    const float* dp_b1 = (const float*)d_in[18];
    const float* dp_w2 = (const float*)d_in[19];
    const float* dp_b2 = (const float*)d_in[20];
    const float* dr_w0 = (const float*)d_in[21];
    const float* dr_b0 = (const float*)d_in[22];
    const float* dr_w1 = (const float*)d_in[23];
    const float* dr_b1 = (const float*)d_in[24];
    const float* dr_w2 = (const float*)d_in[25];
    const float* dr_b2 = (const float*)d_in[26];
    const float* A_w   = (const float*)d_in[27];
    const float* B_w   = (const float*)d_in[28];

    float* out = (float*)d_out;
    const size_t B = 8192, M = 64;
    float* o1 = out;                 // x_k_hat        [B,12]
    float* o2 = o1 + B * 12;         // x_target_hat   [B,M,12]
    float* o3 = o2 + B * M * 12;     // z_pred_seq     [B,M,128]
    float* o4 = o3 + B * M * 128;    // x_pred_hat     [B,M,12]
    float* o5 = o4 + B * M * 12;     // z_target_seq   [B,M,128]

    const int MLP_SMEM  = (2 * TILE * ALD + (KC / 2) * WT2LD) * (int)sizeof(float);
    const int KOOP_SMEM = (16384 + 2 * 4224 + 512 + 128) * (int)sizeof(float);
    cudaFuncSetAttribute(mlp3_kernel, cudaFuncAttributeMaxDynamicSharedMemorySize, MLP_SMEM);
    cudaFuncSetAttribute(koopman_kernel, cudaFuncAttributeMaxDynamicSharedMemorySize, KOOP_SMEM);

    void* zkp = nullptr;
    cudaGetSymbolAddress(&zkp, g_zk);
    float* zk = (float*)zkp;

    const int GBM = (int)(B * M / TILE);  // 16384
    const int GB  = (int)(B / TILE);      // 256

    // encode target sequence -> z_target_seq (o5)
    mlp3_kernel<<<GBM, NTHR, MLP_SMEM>>>(xnext, 12, 0, 3,
        ep_w0, ep_b0, ep_w1, ep_b1, ep_w2, ep_b2, 32, o5, 128, 0);
    mlp3_kernel<<<GBM, NTHR, MLP_SMEM>>>(xnext, 12, 3, 9,
        er_w0, er_b0, er_w1, er_b1, er_w2, er_b2, 96, o5, 128, 32);
    // encode initial state -> g_zk
    mlp3_kernel<<<GB, NTHR, MLP_SMEM>>>(x_k, 12, 0, 3,
        ep_w0, ep_b0, ep_w1, ep_b1, ep_w2, ep_b2, 32, zk, 128, 0);
    mlp3_kernel<<<GB, NTHR, MLP_SMEM>>>(x_k, 12, 3, 9,
        er_w0, er_b0, er_w1, er_b1, er_w2, er_b2, 96, zk, 128, 32);
    // Koopman rollout -> z_pred_seq (o3)
    koopman_kernel<<<GB, NTHR, KOOP_SMEM>>>(zk, u_seq, A_w, B_w, o3);
    // decode z_k -> x_k_hat (o1)
    mlp3_kernel<<<GB, NTHR, MLP_SMEM>>>(zk, 128, 0, 32,
        dp_w0, dp_b0, dp_w1, dp_b1, dp_w2, dp_b2, 3, o1, 12, 0);
    mlp3_kernel<<<GB, NTHR, MLP_SMEM>>>(zk, 128, 32, 96,
        dr_w0, dr_b0, dr_w1, dr_b1, dr_w2, dr_b2, 9, o1, 12, 3);
    // decode z_target -> x_target_hat (o2)
    mlp3_kernel<<<GBM, NTHR, MLP_SMEM>>>(o5, 128, 0, 32,
        dp_w0, dp_b0, dp_w1, dp_b1, dp_w2, dp_b2, 3, o2, 12, 0);
    mlp3_kernel<<<GBM, NTHR, MLP_SMEM>>>(o5, 128, 32, 96,
        dr_w0, dr_b0, dr_w1, dr_b1, dr_w2, dr_b2, 9, o2, 12, 3);
    // decode z_pred -> x_pred_hat (o4)
    mlp3_kernel<<<GBM, NTHR, MLP_SMEM>>>(o3, 128, 0, 32,
        dp_w0, dp_b0, dp_w1, dp_b1, dp_w2, dp_b2, 3, o4, 12, 0);
    mlp3_kernel<<<GBM, NTHR, MLP_SMEM>>>(o3, 128, 32, 96,
        dr_w0, dr_b0, dr_w1, dr_b1, dr_w2, dr_b2, 9, o4, 12, 3);
}

// round 6
// speedup vs baseline: 5.4853x; 5.4853x over previous
#include <cuda_runtime.h>
#include <cuda_bf16.h>
#include <cstdint>
#include <cstddef>

// ======================= scratch (no allocations allowed) ====================
__device__ float g_zk[8192 * 128];
__device__ __nv_bfloat16 g_whi[345088];
__device__ __nv_bfloat16 g_wlo[345088];

// ======================= smem layout (bytes) ================================
// A activations: 64 rows x 264 bf16 (stride 264), hi then lo.
// W chunk: 256 rows x 40 bf16 (stride 40, kc<=32 used), hi then lo.
#define SA 264
#define SW 40
#define AHI_OFF 0
#define ALO_OFF 33792
#define WHI_OFF 67584
#define WLO_OFF 88064
#define SMEM_TOT 108544
#define KC 32

__device__ __forceinline__ uint32_t smem_u32(const void* p) {
    uint32_t a;
    asm("{ .reg .u64 t; cvta.to.shared.u64 t, %1; cvt.u32.u64 %0, t; }"
        : "=r"(a) : "l"(p));
    return a;
}

__device__ __forceinline__ void ldm_x4(uint32_t* r, uint32_t addr) {
    asm volatile("ldmatrix.sync.aligned.m8n8.x4.shared.b16 {%0,%1,%2,%3}, [%4];"
                 : "=r"(r[0]), "=r"(r[1]), "=r"(r[2]), "=r"(r[3]) : "r"(addr));
}

__device__ __forceinline__ void mma16816(float* c, const uint32_t* a,
                                         uint32_t b0, uint32_t b1) {
    asm volatile("mma.sync.aligned.m16n8k16.row.col.f32.bf16.bf16.f32 "
                 "{%0,%1,%2,%3}, {%4,%5,%6,%7}, {%8,%9}, {%0,%1,%2,%3};"
                 : "+f"(c[0]), "+f"(c[1]), "+f"(c[2]), "+f"(c[3])
                 : "r"(a[0]), "r"(a[1]), "r"(a[2]), "r"(a[3]), "r"(b0), "r"(b1));
}

__device__ __forceinline__ uint32_t pack_split(float v0, float v1, uint32_t& lo) {
    __nv_bfloat16 h0 = __float2bfloat16(v0), h1 = __float2bfloat16(v1);
    float r0 = v0 - __bfloat162float(h0), r1 = v1 - __bfloat162float(h1);
    __nv_bfloat16 l0 = __float2bfloat16(r0), l1 = __float2bfloat16(r1);
    lo = (uint32_t)__bfloat16_as_ushort(l0) | ((uint32_t)__bfloat16_as_ushort(l1) << 16);
    return (uint32_t)__bfloat16_as_ushort(h0) | ((uint32_t)__bfloat16_as_ushort(h1) << 16);
}

// ======================= weight pre-split ===================================
__global__ void wprep(const float* __restrict__ W, __nv_bfloat16* __restrict__ hi,
                      __nv_bfloat16* __restrict__ lo, int Nt, int Kt, int Np, int Kp) {
    int i = blockIdx.x * blockDim.x + threadIdx.x;
    if (i >= Np * Kp) return;
    int n = i / Kp, k = i - n * Kp;
    float w = (n < Nt && k < Kt) ? W[n * Kt + k] : 0.f;
    __nv_bfloat16 h = __float2bfloat16(w);
    hi[i] = h;
    lo[i] = __float2bfloat16(w - __bfloat162float(h));
}

// ======================= one GEMM layer (HMMA, 3-term split) =================
// acc[ma][na][4] over warp tile 32x64; warps: wm=wid>>2 (rows), wn=wid&3 (cols).
__device__ __forceinline__ void lay(char* sm, uint32_t sb,
    const uint16_t* __restrict__ wh, const uint16_t* __restrict__ wl,
    int Kp, int Np, int tid, float (&acc)[2][8][4])
{
    #pragma unroll
    for (int a = 0; a < 2; ++a)
        #pragma unroll
        for (int b = 0; b < 8; ++b)
            #pragma unroll
            for (int c = 0; c < 4; ++c) acc[a][b][c] = 0.f;

    const int wid = tid >> 5, lane = tid & 31;
    const int wm = wid >> 2, wn = wid & 3;
    int g_cnt = (Np - wn * 64) / 16;
    if (g_cnt < 0) g_cnt = 0;
    if (g_cnt > 4) g_cnt = 4;

    const int t = lane >> 3, idx = lane & 7;
    const uint32_t aoff = (uint32_t)(((idx + (t & 1) * 8) * SA + (t >> 1) * 8) * 2);
    const uint32_t boff = (uint32_t)(((idx + (t >> 1) * 8) * SW + (t & 1) * 8) * 2);

    for (int k0 = 0; k0 < Kp; k0 += KC) {
        const int kc = min(KC, Kp - k0);
        // stage weight chunk (hi+lo), 2 bf16 per thread-step
        const int wpr = kc >> 1;               // uint32 words per row
        const int words = Np * wpr;
        for (int i = tid; i < words; i += 256) {
            int row = i / wpr, c2 = i - row * wpr;
            uint32_t vh = *(const uint32_t*)&wh[row * Kp + k0 + 2 * c2];
            uint32_t vl = *(const uint32_t*)&wl[row * Kp + k0 + 2 * c2];
            *(uint32_t*)(sm + WHI_OFF + (row * SW + 2 * c2) * 2) = vh;
            *(uint32_t*)(sm + WLO_OFF + (row * SW + 2 * c2) * 2) = vl;
        }
        __syncthreads();

        if (g_cnt > 0) {
            for (int ks = 0; ks < kc; ks += 16) {
                const int kk = k0 + ks;
                uint32_t ah[2][4], al[2][4];
                #pragma unroll
                for (int ma = 0; ma < 2; ++ma) {
                    uint32_t ra = (uint32_t)(((wm * 32 + ma * 16) * SA + kk) * 2) + aoff;
                    ldm_x4(ah[ma], sb + AHI_OFF + ra);
                    ldm_x4(al[ma], sb + ALO_OFF + ra);
                }
                for (int g = 0; g < g_cnt; ++g) {
                    const int n0 = wn * 64 + g * 16;
                    uint32_t rb = (uint32_t)((n0 * SW + ks) * 2) + boff;
                    uint32_t bh[4], bl[4];
                    ldm_x4(bh, sb + WHI_OFF + rb);
                    ldm_x4(bl, sb + WLO_OFF + rb);
                    #pragma unroll
                    for (int ma = 0; ma < 2; ++ma) {
                        mma16816(acc[ma][2 * g],     ah[ma], bh[0], bh[1]);
                        mma16816(acc[ma][2 * g],     ah[ma], bl[0], bl[1]);
                        mma16816(acc[ma][2 * g],     al[ma], bh[0], bh[1]);
                        mma16816(acc[ma][2 * g + 1], ah[ma], bh[2], bh[3]);
                        mma16816(acc[ma][2 * g + 1], ah[ma], bl[2], bl[3]);
                        mma16816(acc[ma][2 * g + 1], al[ma], bh[2], bh[3]);
                    }
                }
            }
        }
        __syncthreads();
    }
}

// relu(acc+bias) -> bf16 hi/lo, in place into A smem
__device__ __forceinline__ void epi_hidden(char* sm, const float* __restrict__ bias,
                                           int tid, float (&acc)[2][8][4])
{
    const int wid = tid >> 5, lane = tid & 31;
    const int wm = wid >> 2, wn = wid & 3;
    const int gid = lane >> 2, tig = lane & 3;
    #pragma unroll
    for (int ma = 0; ma < 2; ++ma)
        #pragma unroll
        for (int na = 0; na < 8; ++na) {
            const float* A4 = acc[ma][na];
            int r = wm * 32 + ma * 16 + gid;
            int c = wn * 64 + na * 8 + 2 * tig;
            float b0 = __ldg(bias + c), b1 = __ldg(bias + c + 1);
            uint32_t lo0, lo1;
            uint32_t hi0 = pack_split(fmaxf(A4[0] + b0, 0.f), fmaxf(A4[1] + b1, 0.f), lo0);
            uint32_t hi1 = pack_split(fmaxf(A4[2] + b0, 0.f), fmaxf(A4[3] + b1, 0.f), lo1);
            *(uint32_t*)(sm + AHI_OFF + (r * SA + c) * 2)       = hi0;
            *(uint32_t*)(sm + ALO_OFF + (r * SA + c) * 2)       = lo0;
            *(uint32_t*)(sm + AHI_OFF + ((r + 8) * SA + c) * 2) = hi1;
            *(uint32_t*)(sm + ALO_OFF + ((r + 8) * SA + c) * 2) = lo1;
        }
    __syncthreads();
}

__device__ __forceinline__ void epi_final(const float* __restrict__ bias, int out_dim,
    float* __restrict__ out, int out_ld, int out_off, int row0, int tid,
    float (&acc)[2][8][4])
{
    const int wid = tid >> 5, lane = tid & 31;
    const int wm = wid >> 2, wn = wid & 3;
    const int gid = lane >> 2, tig = lane & 3;
    #pragma unroll
    for (int ma = 0; ma < 2; ++ma)
        for (int na = 0; na < 8; ++na) {
            int c = wn * 64 + na * 8 + 2 * tig;
            if (c >= out_dim) continue;
            const float* A4 = acc[ma][na];
            int r = row0 + wm * 32 + ma * 16 + gid;
            float b0 = __ldg(bias + c);
            out[(size_t)r * out_ld + out_off + c]       = A4[0] + b0;
            out[(size_t)(r + 8) * out_ld + out_off + c] = A4[2] + b0;
            if (c + 1 < out_dim) {
                float b1 = __ldg(bias + c + 1);
                out[(size_t)r * out_ld + out_off + c + 1]       = A4[1] + b1;
                out[(size_t)(r + 8) * out_ld + out_off + c + 1] = A4[3] + b1;
            }
        }
}

// ======================= fused 3-layer MLP kernel ============================
__global__ void __launch_bounds__(256, 2) mlp_mma(
    const float* __restrict__ in, int in_ld, int in_off, int K1t, int K1p,
    const uint16_t* __restrict__ w1h, const uint16_t* __restrict__ w1l,
    const float* __restrict__ b1,
    const uint16_t* __restrict__ w2h, const uint16_t* __restrict__ w2l,
    const float* __restrict__ b2,
    const uint16_t* __restrict__ w3h, const uint16_t* __restrict__ w3l,
    const float* __restrict__ b3, int Np3, int out_dim,
    float* __restrict__ out, int out_ld, int out_off)
{
    extern __shared__ char sm[];
    const uint32_t sb = smem_u32(sm);
    const int tid = threadIdx.x;
    const int row0 = blockIdx.x * 64;

    // stage layer-1 A (fp32 -> bf16 hi/lo), zero-padded to K1p
    for (int i = tid; i < 64 * K1p; i += 256) {
        int r = i / K1p, k = i - r * K1p;
        float v = (k < K1t) ? in[(size_t)(row0 + r) * in_ld + in_off + k] : 0.f;
        __nv_bfloat16 h = __float2bfloat16(v);
        __nv_bfloat16 l = __float2bfloat16(v - __bfloat162float(h));
        *(uint16_t*)(sm + AHI_OFF + (r * SA + k) * 2) = __bfloat16_as_ushort(h);
        *(uint16_t*)(sm + ALO_OFF + (r * SA + k) * 2) = __bfloat16_as_ushort(l);
    }
    __syncthreads();

    float acc[2][8][4];
    lay(sm, sb, w1h, w1l, K1p, 256, tid, acc);
    epi_hidden(sm, b1, tid, acc);
    lay(sm, sb, w2h, w2l, 256, 256, tid, acc);
    epi_hidden(sm, b2, tid, acc);
    lay(sm, sb, w3h, w3l, 256, Np3, tid, acc);
    epi_final(b3, out_dim, out, out_ld, out_off, row0, tid, acc);
}

// ======================= Koopman recurrence (fp32, proven) ===================
union F2U { float2 f; unsigned long long u; };
__device__ __forceinline__ float2 ffma2(float2 a, float2 b, float2 c) {
    F2U A, Bv, C; A.f = a; Bv.f = b; C.f = c;
    asm("fma.rn.f32x2 %0, %1, %2, %0;" : "+l"(C.u) : "l"(A.u), "l"(Bv.u));
    return C.f;
}

__global__ void __launch_bounds__(256, 2) koopman_kernel(
    const float* __restrict__ zk, const float* __restrict__ u,
    const float* __restrict__ A, const float* __restrict__ Bw,
    float* __restrict__ zpred)
{
    extern __shared__ float smem[];
    float* As = smem;
    float* z0 = As + 16384;
    float* z1 = z0 + 4224;
    float* bw = z1 + 4224;
    float* us = bw + 512;

    const int tid  = threadIdx.x;
    const int row0 = blockIdx.x * 32;

    for (int i = tid; i < 16384; i += 256) {
        int o = i & 127, k = i >> 7;
        As[k * 128 + o] = A[o * 128 + k];
    }
    for (int i = tid; i < 512; i += 256) {
        int o = i & 127, j = i >> 7;
        bw[j * 128 + o] = Bw[o * 4 + j];
    }
    for (int i = tid; i < 4096; i += 256) {
        int r = i >> 7, k = i & 127;
        z0[r * 132 + k] = zk[(size_t)(row0 + r) * 128 + k];
    }
    const int oc = (tid & 63) * 2;
    const int rg = tid >> 6;
    __syncthreads();

    for (int s = 0; s < 64; ++s) {
        if (tid < 128) {
            int r = tid >> 2, j = tid & 3;
            us[r * 4 + j] = u[((size_t)(row0 + r) * 64 + s) * 4 + j];
        }
        __syncthreads();
        const float* zc = (s & 1) ? z1 : z0;
        float*       zn = (s & 1) ? z0 : z1;

        float2 acc[8];
        #pragma unroll
        for (int r = 0; r < 8; ++r) acc[r] = make_float2(0.f, 0.f);

        #pragma unroll
        for (int j = 0; j < 4; ++j) {
            float2 bv = *(const float2*)&bw[j * 128 + oc];
            #pragma unroll
            for (int r = 0; r < 8; ++r) {
                float uv = us[(rg * 8 + r) * 4 + j];
                acc[r] = ffma2(bv, make_float2(uv, uv), acc[r]);
            }
        }
        for (int k = 0; k < 128; ++k) {
            float2 av = *(const float2*)&As[k * 128 + oc];
            #pragma unroll
            for (int r = 0; r < 8; ++r) {
                float zv = zc[(rg * 8 + r) * 132 + k];
                acc[r] = ffma2(av, make_float2(zv, zv), acc[r]);
            }
        }
        #pragma unroll
        for (int r = 0; r < 8; ++r) {
            int rr = rg * 8 + r;
            *(float2*)&zn[rr * 132 + oc] = acc[r];
            *(float2*)&zpred[(((size_t)(row0 + rr)) * 64 + s) * 128 + oc] = acc[r];
        }
        __syncthreads();
    }
}

// ======================= host launcher ======================================
extern "C" void kernel_launch(void* const* d_in, const int* in_sizes, int n_in,
                              void* d_out, int out_size) {
    (void)in_sizes; (void)n_in; (void)out_size;
    const float* x_k   = (const float*)d_in[0];
    const float* u_seq = (const float*)d_in[1];
    const float* xnext = (const float*)d_in[2];
    const float* W[12] = {
        (const float*)d_in[3],  (const float*)d_in[5],  (const float*)d_in[7],
        (const float*)d_in[9],  (const float*)d_in[11], (const float*)d_in[13],
        (const float*)d_in[15], (const float*)d_in[17], (const float*)d_in[19],
        (const float*)d_in[21], (const float*)d_in[23], (const float*)d_in[25]
    };
    const float* Bv[12] = {
        (const float*)d_in[4],  (const float*)d_in[6],  (const float*)d_in[8],
        (const float*)d_in[10], (const float*)d_in[12], (const float*)d_in[14],
        (const float*)d_in[16], (const float*)d_in[18], (const float*)d_in[20],
        (const float*)d_in[22], (const float*)d_in[24], (const float*)d_in[26]
    };
    const float* A_w = (const float*)d_in[27];
    const float* B_w = (const float*)d_in[28];

    float* out = (float*)d_out;
    const size_t B = 8192, M = 64;
    float* o1 = out;                 // x_k_hat        [B,12]
    float* o2 = o1 + B * 12;         // x_target_hat   [B,M,12]
    float* o3 = o2 + B * M * 12;     // z_pred_seq     [B,M,128]
    float* o4 = o3 + B * M * 128;    // x_pred_hat     [B,M,12]
    float* o5 = o4 + B * M * 12;     // z_target_seq   [B,M,128]

    void *whp, *wlp, *zkp;
    cudaGetSymbolAddress(&whp, g_whi);
    cudaGetSymbolAddress(&wlp, g_wlo);
    cudaGetSymbolAddress(&zkp, g_zk);
    __nv_bfloat16* wh = (__nv_bfloat16*)whp;
    __nv_bfloat16* wl = (__nv_bfloat16*)wlp;
    float* zk = (float*)zkp;

    // {off, Nt, Kt, Np, Kp}
    static const int T[12][5] = {
        {0,      256, 3,   256, 16},  {4096,   256, 256, 256, 256}, {69632,  32,  256, 32,  256},
        {77824,  256, 9,   256, 16},  {81920,  256, 256, 256, 256}, {147456, 96,  256, 96,  256},
        {172032, 256, 32,  256, 32},  {180224, 256, 256, 256, 256}, {245760, 3,   256, 16,  256},
        {249856, 256, 96,  256, 96},  {274432, 256, 256, 256, 256}, {339968, 9,   256, 16,  256}
    };
    for (int i = 0; i < 12; ++i) {
        int elems = T[i][3] * T[i][4];
        wprep<<<(elems + 255) / 256, 256>>>(W[i], wh + T[i][0], wl + T[i][0],
                                            T[i][1], T[i][2], T[i][3], T[i][4]);
    }

    const int KOOP_SMEM = (16384 + 2 * 4224 + 512 + 128) * (int)sizeof(float);
    cudaFuncSetAttribute(mlp_mma, cudaFuncAttributeMaxDynamicSharedMemorySize, SMEM_TOT);
    cudaFuncSetAttribute(koopman_kernel, cudaFuncAttributeMaxDynamicSharedMemorySize, KOOP_SMEM);

    const int GBM = (int)(B * M / 64);  // 8192
    const int GB  = (int)(B / 64);      // 128

    #define RUN(grid, inp, ild, ioff, K1t, K1p, net, Np3, od, op, old, ooff) \
        mlp_mma<<<grid, 256, SMEM_TOT>>>(inp, ild, ioff, K1t, K1p, \
            (const uint16_t*)(wh + T[(net)*3][0]),   (const uint16_t*)(wl + T[(net)*3][0]),   Bv[(net)*3], \
            (const uint16_t*)(wh + T[(net)*3+1][0]), (const uint16_t*)(wl + T[(net)*3+1][0]), Bv[(net)*3+1], \
            (const uint16_t*)(wh + T[(net)*3+2][0]), (const uint16_t*)(wl + T[(net)*3+2][0]), Bv[(net)*3+2], \
            Np3, od, op, old, ooff)

    // encode target seq -> o5 ; encode x_k -> zk
    RUN(GBM, xnext, 12, 0, 3,  16, 0, 32, 32, o5, 128, 0);
    RUN(GBM, xnext, 12, 3, 9,  16, 1, 96, 96, o5, 128, 32);
    RUN(GB,  x_k,   12, 0, 3,  16, 0, 32, 32, zk, 128, 0);
    RUN(GB,  x_k,   12, 3, 9,  16, 1, 96, 96, zk, 128, 32);
    // Koopman rollout -> o3
    koopman_kernel<<<(int)(B / 32), 256, KOOP_SMEM>>>(zk, u_seq, A_w, B_w, o3);
    // decode z_k -> o1
    RUN(GB,  zk, 128, 0,  32, 32, 2, 16, 3, o1, 12, 0);
    RUN(GB,  zk, 128, 32, 96, 96, 3, 16, 9, o1, 12, 3);
    // decode z_target -> o2
    RUN(GBM, o5, 128, 0,  32, 32, 2, 16, 3, o2, 12, 0);
    RUN(GBM, o5, 128, 32, 96, 96, 3, 16, 9, o2, 12, 3);
    // decode z_pred -> o4
    RUN(GBM, o3, 128, 0,  32, 32, 2, 16, 3, o4, 12, 0);
    RUN(GBM, o3, 128, 32, 96, 96, 3, 16, 9, o4, 12, 3);
    #undef RUN
}

// round 7
// speedup vs baseline: 5.8874x; 1.0733x over previous
#include <cuda_runtime.h>
#include <cuda_bf16.h>
#include <cstdint>
#include <cstddef>

// ======================= scratch (no allocations allowed) ====================
__device__ float g_zk[8192 * 128];
__device__ __align__(16) __nv_bfloat16 g_whi[345088];
__device__ __align__(16) __nv_bfloat16 g_wlo[345088];

// ======================= smem layout (bytes) ================================
// A: 128 rows x 264 bf16 (stride 264), hi then lo.      2 x 67584
// W: double-buffered chunks, 256 rows x 40 bf16 stride, hi then lo per slot.
#define NTHR 512
#define ROWS 128
#define SA 264
#define SW 40
#define KC 32
#define AHI_OFF 0
#define ALO_OFF 67584
#define WOFF    135168
#define WHALF   20480
#define WSLOT   40960
#define SMEM_TOT 217088

__device__ __forceinline__ uint32_t smem_u32(const void* p) {
    uint32_t a;
    asm("{ .reg .u64 t; cvta.to.shared.u64 t, %1; cvt.u32.u64 %0, t; }"
        : "=r"(a) : "l"(p));
    return a;
}
__device__ __forceinline__ void ldm_x4(uint32_t* r, uint32_t addr) {
    asm volatile("ldmatrix.sync.aligned.m8n8.x4.shared.b16 {%0,%1,%2,%3}, [%4];"
                 : "=r"(r[0]), "=r"(r[1]), "=r"(r[2]), "=r"(r[3]) : "r"(addr));
}
__device__ __forceinline__ void mma16816(float* c, const uint32_t* a,
                                         uint32_t b0, uint32_t b1) {
    asm volatile("mma.sync.aligned.m16n8k16.row.col.f32.bf16.bf16.f32 "
                 "{%0,%1,%2,%3}, {%4,%5,%6,%7}, {%8,%9}, {%0,%1,%2,%3};"
                 : "+f"(c[0]), "+f"(c[1]), "+f"(c[2]), "+f"(c[3])
                 : "r"(a[0]), "r"(a[1]), "r"(a[2]), "r"(a[3]), "r"(b0), "r"(b1));
}
__device__ __forceinline__ void cpa16(uint32_t dst, const void* src) {
    asm volatile("cp.async.cg.shared.global [%0], [%1], 16;" :: "r"(dst), "l"(src));
}
#define CP_COMMIT() asm volatile("cp.async.commit_group;" ::: "memory")
#define CP_WAIT0()  asm volatile("cp.async.wait_group 0;" ::: "memory")

__device__ __forceinline__ uint32_t pack_split(float v0, float v1, uint32_t& lo) {
    __nv_bfloat16 h0 = __float2bfloat16(v0), h1 = __float2bfloat16(v1);
    float r0 = v0 - __bfloat162float(h0), r1 = v1 - __bfloat162float(h1);
    __nv_bfloat16 l0 = __float2bfloat16(r0), l1 = __float2bfloat16(r1);
    lo = (uint32_t)__bfloat16_as_ushort(l0) | ((uint32_t)__bfloat16_as_ushort(l1) << 16);
    return (uint32_t)__bfloat16_as_ushort(h0) | ((uint32_t)__bfloat16_as_ushort(h1) << 16);
}

// ======================= fused weight pre-split (ONE launch) =================
// {off, Nt, Kt, Np, Kp} per layer, 4 networks x 3 layers
__device__ const int dT[12][5] = {
    {0,      256, 3,   256, 16},  {4096,   256, 256, 256, 256}, {69632,  32,  256, 32,  256},
    {77824,  256, 9,   256, 16},  {81920,  256, 256, 256, 256}, {147456, 96,  256, 96,  256},
    {172032, 256, 32,  256, 32},  {180224, 256, 256, 256, 256}, {245760, 3,   256, 16,  256},
    {249856, 256, 96,  256, 96},  {274432, 256, 256, 256, 256}, {339968, 9,   256, 16,  256}
};
struct WP { const float* w[12]; };

__global__ void wprep_all(WP p, __nv_bfloat16* __restrict__ hi,
                          __nv_bfloat16* __restrict__ lo) {
    const int net = blockIdx.y;
    const int off = dT[net][0], Nt = dT[net][1], Kt = dT[net][2];
    const int Np = dT[net][3], Kp = dT[net][4];
    const float* W = p.w[net];
    for (int i = blockIdx.x * 256 + threadIdx.x; i < Np * Kp; i += gridDim.x * 256) {
        int n = i / Kp, k = i - n * Kp;
        float w = (n < Nt && k < Kt) ? W[n * Kt + k] : 0.f;
        __nv_bfloat16 h = __float2bfloat16(w);
        hi[off + i] = h;
        lo[off + i] = __float2bfloat16(w - __bfloat162float(h));
    }
}

// ======================= weight chunk staging (cp.async) =====================
__device__ __forceinline__ void stage_w(uint32_t sb, int slot,
    const uint16_t* __restrict__ wh, const uint16_t* __restrict__ wl,
    int Kp, int Np, int k0, int kc, int tid)
{
    const int spr = kc >> 3;          // 16B segments per row (2 or 4)
    const int per = Np * spr;
    const uint32_t base = sb + WOFF + slot * WSLOT;
    for (int i = tid; i < 2 * per; i += NTHR) {
        int m = (i >= per);
        int j = i - m * per;
        int row = j / spr, seg = j - row * spr;
        const uint16_t* src = (m ? wl : wh) + row * Kp + k0 + seg * 8;
        cpa16(base + m * WHALF + row * (SW * 2) + seg * 16, src);
    }
}

// ======================= one GEMM layer (HMMA, 3-term split) =================
// warps: wm=wid>>2 (4 row groups of 32), wn=wid&3 (4 col groups of 64)
__device__ __forceinline__ void lay(char* sm, uint32_t sb,
    const uint16_t* __restrict__ wh, const uint16_t* __restrict__ wl,
    int Kp, int Np, int tid, float (&acc)[2][8][4])
{
    #pragma unroll
    for (int a = 0; a < 2; ++a)
        #pragma unroll
        for (int b = 0; b < 8; ++b)
            #pragma unroll
            for (int c = 0; c < 4; ++c) acc[a][b][c] = 0.f;

    const int wid = tid >> 5, lane = tid & 31;
    const int wm = wid >> 2, wn = wid & 3;
    int g_cnt = (Np - wn * 64) / 16;
    if (g_cnt < 0) g_cnt = 0;
    if (g_cnt > 4) g_cnt = 4;

    const int t = lane >> 3, idx = lane & 7;
    const uint32_t aoff = (uint32_t)(((idx + (t & 1) * 8) * SA + (t >> 1) * 8) * 2);
    const uint32_t boff = (uint32_t)(((idx + (t >> 1) * 8) * SW + (t & 1) * 8) * 2);

    const int chunks = (Kp + KC - 1) / KC;
    { int kc0 = min(KC, Kp); stage_w(sb, 0, wh, wl, Kp, Np, 0, kc0, tid); CP_COMMIT(); }

    for (int c = 0; c < chunks; ++c) {
        CP_WAIT0();
        __syncthreads();
        if (c + 1 < chunks) {
            int kcn = min(KC, Kp - (c + 1) * KC);
            stage_w(sb, (c + 1) & 1, wh, wl, Kp, Np, (c + 1) * KC, kcn, tid);
            CP_COMMIT();
        }
        const int kc = min(KC, Kp - c * KC);
        if (g_cnt > 0) {
            const uint32_t wbase = sb + WOFF + (uint32_t)(c & 1) * WSLOT;
            for (int ks = 0; ks < kc; ks += 16) {
                const int kk = c * KC + ks;
                uint32_t ah[2][4], al[2][4];
                #pragma unroll
                for (int ma = 0; ma < 2; ++ma) {
                    uint32_t ra = (uint32_t)(((wm * 32 + ma * 16) * SA + kk) * 2) + aoff;
                    ldm_x4(ah[ma], sb + AHI_OFF + ra);
                    ldm_x4(al[ma], sb + ALO_OFF + ra);
                }
                for (int g = 0; g < g_cnt; ++g) {
                    const int n0 = wn * 64 + g * 16;
                    uint32_t rb = (uint32_t)((n0 * SW + ks) * 2) + boff;
                    uint32_t bh[4], bl[4];
                    ldm_x4(bh, wbase + rb);
                    ldm_x4(bl, wbase + WHALF + rb);
                    #pragma unroll
                    for (int ma = 0; ma < 2; ++ma) {
                        mma16816(acc[ma][2 * g],     ah[ma], bh[0], bh[1]);
                        mma16816(acc[ma][2 * g],     ah[ma], bl[0], bl[1]);
                        mma16816(acc[ma][2 * g],     al[ma], bh[0], bh[1]);
                        mma16816(acc[ma][2 * g + 1], ah[ma], bh[2], bh[3]);
                        mma16816(acc[ma][2 * g + 1], ah[ma], bl[2], bl[3]);
                        mma16816(acc[ma][2 * g + 1], al[ma], bh[2], bh[3]);
                    }
                }
            }
        }
    }
    __syncthreads();
}

// relu(acc+bias) -> bf16 hi/lo, in place into A smem
__device__ __forceinline__ void epi_hidden(char* sm, const float* __restrict__ bias,
                                           int tid, float (&acc)[2][8][4])
{
    const int wid = tid >> 5, lane = tid & 31;
    const int wm = wid >> 2, wn = wid & 3;
    const int gid = lane >> 2, tig = lane & 3;
    #pragma unroll
    for (int ma = 0; ma < 2; ++ma)
        #pragma unroll
        for (int na = 0; na < 8; ++na) {
            const float* A4 = acc[ma][na];
            int r = wm * 32 + ma * 16 + gid;
            int c = wn * 64 + na * 8 + 2 * tig;
            float b0 = __ldg(bias + c), b1 = __ldg(bias + c + 1);
            uint32_t lo0, lo1;
            uint32_t hi0 = pack_split(fmaxf(A4[0] + b0, 0.f), fmaxf(A4[1] + b1, 0.f), lo0);
            uint32_t hi1 = pack_split(fmaxf(A4[2] + b0, 0.f), fmaxf(A4[3] + b1, 0.f), lo1);
            *(uint32_t*)(sm + AHI_OFF + (r * SA + c) * 2)       = hi0;
            *(uint32_t*)(sm + ALO_OFF + (r * SA + c) * 2)       = lo0;
            *(uint32_t*)(sm + AHI_OFF + ((r + 8) * SA + c) * 2) = hi1;
            *(uint32_t*)(sm + ALO_OFF + ((r + 8) * SA + c) * 2) = lo1;
        }
    __syncthreads();
}

__device__ __forceinline__ void epi_final(const float* __restrict__ bias, int out_dim,
    float* __restrict__ out, int out_ld, int out_off, int row0, int tid,
    float (&acc)[2][8][4])
{
    const int wid = tid >> 5, lane = tid & 31;
    const int wm = wid >> 2, wn = wid & 3;
    const int gid = lane >> 2, tig = lane & 3;
    #pragma unroll
    for (int ma = 0; ma < 2; ++ma)
        for (int na = 0; na < 8; ++na) {
            int c = wn * 64 + na * 8 + 2 * tig;
            if (c >= out_dim) continue;
            const float* A4 = acc[ma][na];
            int r = row0 + wm * 32 + ma * 16 + gid;
            float b0 = __ldg(bias + c);
            out[(size_t)r * out_ld + out_off + c]       = A4[0] + b0;
            out[(size_t)(r + 8) * out_ld + out_off + c] = A4[2] + b0;
            if (c + 1 < out_dim) {
                float b1 = __ldg(bias + c + 1);
                out[(size_t)r * out_ld + out_off + c + 1]       = A4[1] + b1;
                out[(size_t)(r + 8) * out_ld + out_off + c + 1] = A4[3] + b1;
            }
        }
}

// ======================= fused 3-layer MLP kernel ============================
__global__ void __launch_bounds__(NTHR, 1) mlp_mma(
    const float* __restrict__ in, int in_ld, int in_off, int K1t, int K1p,
    const uint16_t* __restrict__ w1h, const uint16_t* __restrict__ w1l,
    const float* __restrict__ b1,
    const uint16_t* __restrict__ w2h, const uint16_t* __restrict__ w2l,
    const float* __restrict__ b2,
    const uint16_t* __restrict__ w3h, const uint16_t* __restrict__ w3l,
    const float* __restrict__ b3, int Np3, int out_dim,
    float* __restrict__ out, int out_ld, int out_off)
{
    extern __shared__ char sm[];
    const uint32_t sb = smem_u32(sm);
    const int tid = threadIdx.x;
    const int row0 = blockIdx.x * ROWS;

    // stage layer-1 A (fp32 -> bf16 hi/lo), zero-padded to K1p
    for (int i = tid; i < ROWS * K1p; i += NTHR) {
        int r = i / K1p, k = i - r * K1p;
        float v = (k < K1t) ? in[(size_t)(row0 + r) * in_ld + in_off + k] : 0.f;
        __nv_bfloat16 h = __float2bfloat16(v);
        __nv_bfloat16 l = __float2bfloat16(v - __bfloat162float(h));
        *(uint16_t*)(sm + AHI_OFF + (r * SA + k) * 2) = __bfloat16_as_ushort(h);
        *(uint16_t*)(sm + ALO_OFF + (r * SA + k) * 2) = __bfloat16_as_ushort(l);
    }
    __syncthreads();

    float acc[2][8][4];
    lay(sm, sb, w1h, w1l, K1p, 256, tid, acc);
    epi_hidden(sm, b1, tid, acc);
    lay(sm, sb, w2h, w2l, 256, 256, tid, acc);
    epi_hidden(sm, b2, tid, acc);
    lay(sm, sb, w3h, w3l, 256, Np3, tid, acc);
    epi_final(b3, out_dim, out, out_ld, out_off, row0, tid, acc);
}

// ======================= Koopman recurrence (fp32, proven) ===================
union F2U { float2 f; unsigned long long u; };
__device__ __forceinline__ float2 ffma2(float2 a, float2 b, float2 c) {
    F2U A, Bv, C; A.f = a; Bv.f = b; C.f = c;
    asm("fma.rn.f32x2 %0, %1, %2, %0;" : "+l"(C.u) : "l"(A.u), "l"(Bv.u));
    return C.f;
}

__global__ void __launch_bounds__(256, 2) koopman_kernel(
    const float* __restrict__ zk, const float* __restrict__ u,
    const float* __restrict__ A, const float* __restrict__ Bw,
    float* __restrict__ zpred)
{
    extern __shared__ float smem[];
    float* As = smem;
    float* z0 = As + 16384;
    float* z1 = z0 + 4224;
    float* bw = z1 + 4224;
    float* us = bw + 512;

    const int tid  = threadIdx.x;
    const int row0 = blockIdx.x * 32;

    for (int i = tid; i < 16384; i += 256) {
        int o = i & 127, k = i >> 7;
        As[k * 128 + o] = A[o * 128 + k];
    }
    for (int i = tid; i < 512; i += 256) {
        int o = i & 127, j = i >> 7;
        bw[j * 128 + o] = Bw[o * 4 + j];
    }
    for (int i = tid; i < 4096; i += 256) {
        int r = i >> 7, k = i & 127;
        z0[r * 132 + k] = zk[(size_t)(row0 + r) * 128 + k];
    }
    const int oc = (tid & 63) * 2;
    const int rg = tid >> 6;
    __syncthreads();

    for (int s = 0; s < 64; ++s) {
        if (tid < 128) {
            int r = tid >> 2, j = tid & 3;
            us[r * 4 + j] = u[((size_t)(row0 + r) * 64 + s) * 4 + j];
        }
        __syncthreads();
        const float* zc = (s & 1) ? z1 : z0;
        float*       zn = (s & 1) ? z0 : z1;

        float2 acc[8];
        #pragma unroll
        for (int r = 0; r < 8; ++r) acc[r] = make_float2(0.f, 0.f);

        #pragma unroll
        for (int j = 0; j < 4; ++j) {
            float2 bv = *(const float2*)&bw[j * 128 + oc];
            #pragma unroll
            for (int r = 0; r < 8; ++r) {
                float uv = us[(rg * 8 + r) * 4 + j];
                acc[r] = ffma2(bv, make_float2(uv, uv), acc[r]);
            }
        }
        for (int k = 0; k < 128; ++k) {
            float2 av = *(const float2*)&As[k * 128 + oc];
            #pragma unroll
            for (int r = 0; r < 8; ++r) {
                float zv = zc[(rg * 8 + r) * 132 + k];
                acc[r] = ffma2(av, make_float2(zv, zv), acc[r]);
            }
        }
        #pragma unroll
        for (int r = 0; r < 8; ++r) {
            int rr = rg * 8 + r;
            *(float2*)&zn[rr * 132 + oc] = acc[r];
            *(float2*)&zpred[(((size_t)(row0 + rr)) * 64 + s) * 128 + oc] = acc[r];
        }
        __syncthreads();
    }
}

// ======================= host launcher ======================================
extern "C" void kernel_launch(void* const* d_in, const int* in_sizes, int n_in,
                              void* d_out, int out_size) {
    (void)in_sizes; (void)n_in; (void)out_size;
    const float* x_k   = (const float*)d_in[0];
    const float* u_seq = (const float*)d_in[1];
    const float* xnext = (const float*)d_in[2];
    WP wp;
    wp.w[0]  = (const float*)d_in[3];  wp.w[1]  = (const float*)d_in[5];
    wp.w[2]  = (const float*)d_in[7];  wp.w[3]  = (const float*)d_in[9];
    wp.w[4]  = (const float*)d_in[11]; wp.w[5]  = (const float*)d_in[13];
    wp.w[6]  = (const float*)d_in[15]; wp.w[7]  = (const float*)d_in[17];
    wp.w[8]  = (const float*)d_in[19]; wp.w[9]  = (const float*)d_in[21];
    wp.w[10] = (const float*)d_in[23]; wp.w[11] = (const float*)d_in[25];
    const float* Bv[12] = {
        (const float*)d_in[4],  (const float*)d_in[6],  (const float*)d_in[8],
        (const float*)d_in[10], (const float*)d_in[12], (const float*)d_in[14],
        (const float*)d_in[16], (const float*)d_in[18], (const float*)d_in[20],
        (const float*)d_in[22], (const float*)d_in[24], (const float*)d_in[26]
    };
    const float* A_w = (const float*)d_in[27];
    const float* B_w = (const float*)d_in[28];

    float* out = (float*)d_out;
    const size_t B = 8192, M = 64;
    float* o1 = out;                 // x_k_hat        [B,12]
    float* o2 = o1 + B * 12;         // x_target_hat   [B,M,12]
    float* o3 = o2 + B * M * 12;     // z_pred_seq     [B,M,128]
    float* o4 = o3 + B * M * 128;    // x_pred_hat     [B,M,12]
    float* o5 = o4 + B * M * 12;     // z_target_seq   [B,M,128]

    void *whp, *wlp, *zkp;
    cudaGetSymbolAddress(&whp, g_whi);
    cudaGetSymbolAddress(&wlp, g_wlo);
    cudaGetSymbolAddress(&zkp, g_zk);
    __nv_bfloat16* wh = (__nv_bfloat16*)whp;
    __nv_bfloat16* wl = (__nv_bfloat16*)wlp;
    float* zk = (float*)zkp;

    static const int T[12] = {0, 4096, 69632, 77824, 81920, 147456,
                              172032, 180224, 245760, 249856, 274432, 339968};

    const int KOOP_SMEM = (16384 + 2 * 4224 + 512 + 128) * (int)sizeof(float);
    cudaFuncSetAttribute(mlp_mma, cudaFuncAttributeMaxDynamicSharedMemorySize, SMEM_TOT);
    cudaFuncSetAttribute(koopman_kernel, cudaFuncAttributeMaxDynamicSharedMemorySize, KOOP_SMEM);

    const int GBM = (int)(B * M / ROWS);  // 4096
    const int GB  = (int)(B / ROWS);      // 64

    #define RUN(grid, inp, ild, ioff, K1t, K1p, net, Np3, od, op, old, ooff) \
        mlp_mma<<<grid, NTHR, SMEM_TOT>>>(inp, ild, ioff, K1t, K1p, \
            (const uint16_t*)(wh + T[(net)*3]),   (const uint16_t*)(wl + T[(net)*3]),   Bv[(net)*3], \
            (const uint16_t*)(wh + T[(net)*3+1]), (const uint16_t*)(wl + T[(net)*3+1]), Bv[(net)*3+1], \
            (const uint16_t*)(wh + T[(net)*3+2]), (const uint16_t*)(wl + T[(net)*3+2]), Bv[(net)*3+2], \
            Np3, od, op, old, ooff)

    // 1: weight pre-split (single launch)
    wprep_all<<<dim3(256, 12), 256>>>(wp, wh, wl);
    // 2,3: encode initial state -> zk
    RUN(GB,  x_k,   12, 0, 3,  16, 0, 32, 32, zk, 128, 0);
    RUN(GB,  x_k,   12, 3, 9,  16, 1, 96, 96, zk, 128, 32);
    // 4: Koopman rollout -> o3
    koopman_kernel<<<(int)(B / 32), 256, KOOP_SMEM>>>(zk, u_seq, A_w, B_w, o3);
    // 5,6: encode target seq -> o5   (launch #6 = ncu capture slot)
    RUN(GBM, xnext, 12, 0, 3,  16, 0, 32, 32, o5, 128, 0);
    RUN(GBM, xnext, 12, 3, 9,  16, 1, 96, 96, o5, 128, 32);
    // decode z_k -> o1
    RUN(GB,  zk, 128, 0,  32, 32, 2, 16, 3, o1, 12, 0);
    RUN(GB,  zk, 128, 32, 96, 96, 3, 16, 9, o1, 12, 3);
    // decode z_target -> o2
    RUN(GBM, o5, 128, 0,  32, 32, 2, 16, 3, o2, 12, 0);
    RUN(GBM, o5, 128, 32, 96, 96, 3, 16, 9, o2, 12, 3);
    // decode z_pred -> o4
    RUN(GBM, o3, 128, 0,  32, 32, 2, 16, 3, o4, 12, 0);
    RUN(GBM, o3, 128, 32, 96, 96, 3, 16, 9, o4, 12, 3);
    #undef RUN
}

// round 9
// speedup vs baseline: 7.8092x; 1.3264x over previous
#include <cuda_runtime.h>
#include <cuda_fp16.h>
#include <cstdint>
#include <cstddef>

// ======================= scratch (no allocations allowed) ====================
__device__ float g_zk[8192 * 128];
__device__ __align__(16) __half g_w[345088];

// ======================= smem layout (bytes) ================================
// A: 128 rows x 264 fp16 (stride 264), hi then lo.       2 x 67584
// W: double-buffered chunks, 256 rows x 40 fp16 stride.  2 x 20480
#define NTHR 512
#define ROWS 128
#define SA 264
#define SW 40
#define KC 32
#define AHI_OFF 0
#define ALO_OFF 67584
#define WOFF    135168
#define WSLOT   20480
#define SMEM_TOT 176128

__device__ __forceinline__ uint32_t smem_u32(const void* p) {
    uint32_t a;
    asm("{ .reg .u64 t; cvta.to.shared.u64 t, %1; cvt.u32.u64 %0, t; }"
        : "=r"(a) : "l"(p));
    return a;
}
__device__ __forceinline__ void ldm_x4(uint32_t* r, uint32_t addr) {
    asm volatile("ldmatrix.sync.aligned.m8n8.x4.shared.b16 {%0,%1,%2,%3}, [%4];"
                 : "=r"(r[0]), "=r"(r[1]), "=r"(r[2]), "=r"(r[3]) : "r"(addr));
}
__device__ __forceinline__ void mma16816(float* c, const uint32_t* a,
                                         uint32_t b0, uint32_t b1) {
    asm volatile("mma.sync.aligned.m16n8k16.row.col.f32.f16.f16.f32 "
                 "{%0,%1,%2,%3}, {%4,%5,%6,%7}, {%8,%9}, {%0,%1,%2,%3};"
                 : "+f"(c[0]), "+f"(c[1]), "+f"(c[2]), "+f"(c[3])
                 : "r"(a[0]), "r"(a[1]), "r"(a[2]), "r"(a[3]), "r"(b0), "r"(b1));
}
__device__ __forceinline__ void cpa16(uint32_t dst, const void* src) {
    asm volatile("cp.async.cg.shared.global [%0], [%1], 16;" :: "r"(dst), "l"(src));
}
#define CP_COMMIT() asm volatile("cp.async.commit_group;" ::: "memory")
#define CP_WAIT0()  asm volatile("cp.async.wait_group 0;" ::: "memory")

__device__ __forceinline__ uint32_t pack_split(float v0, float v1, uint32_t& lo) {
    __half h0 = __float2half_rn(v0), h1 = __float2half_rn(v1);
    float r0 = v0 - __half2float(h0), r1 = v1 - __half2float(h1);
    __half l0 = __float2half_rn(r0), l1 = __float2half_rn(r1);
    lo = (uint32_t)__half_as_ushort(l0) | ((uint32_t)__half_as_ushort(l1) << 16);
    return (uint32_t)__half_as_ushort(h0) | ((uint32_t)__half_as_ushort(h1) << 16);
}

// ======================= fused weight pre-split (ONE launch) =================
// {off, Nt, Kt, Np, Kp} per layer, 4 networks x 3 layers
__device__ const int dT[12][5] = {
    {0,      256, 3,   256, 16},  {4096,   256, 256, 256, 256}, {69632,  32,  256, 32,  256},
    {77824,  256, 9,   256, 16},  {81920,  256, 256, 256, 256}, {147456, 96,  256, 96,  256},
    {172032, 256, 32,  256, 32},  {180224, 256, 256, 256, 256}, {245760, 3,   256, 16,  256},
    {249856, 256, 96,  256, 96},  {274432, 256, 256, 256, 256}, {339968, 9,   256, 16,  256}
};
struct WP { const float* w[12]; };

__global__ void wprep_all(WP p, __half* __restrict__ wq) {
    const int net = blockIdx.y;
    const int off = dT[net][0], Nt = dT[net][1], Kt = dT[net][2];
    const int Np = dT[net][3], Kp = dT[net][4];
    const float* W = p.w[net];
    for (int i = blockIdx.x * 256 + threadIdx.x; i < Np * Kp; i += gridDim.x * 256) {
        int n = i / Kp, k = i - n * Kp;
        float w = (n < Nt && k < Kt) ? W[n * Kt + k] : 0.f;
        wq[off + i] = __float2half_rn(w);
    }
}

// ======================= weight chunk staging (cp.async) =====================
__device__ __forceinline__ void stage_w(uint32_t sb, int slot,
    const uint16_t* __restrict__ w, int Kp, int Np, int k0, int kc, int tid)
{
    const int spr = kc >> 3;          // 16B segments per row (2 or 4)
    const int per = Np * spr;
    const uint32_t base = sb + WOFF + slot * WSLOT;
    for (int i = tid; i < per; i += NTHR) {
        int row = i / spr, seg = i - row * spr;
        cpa16(base + row * (SW * 2) + seg * 16, w + row * Kp + k0 + seg * 8);
    }
}

// ======================= one GEMM layer (HMMA, fp16 2-term split) ============
// warps: wm=wid>>2 (4 row groups of 32), wn=wid&3 (4 col groups of 64)
__device__ __forceinline__ void lay(char* sm, uint32_t sb,
    const uint16_t* __restrict__ w, int Kp, int Np, int tid, float (&acc)[2][8][4])
{
    #pragma unroll
    for (int a = 0; a < 2; ++a)
        #pragma unroll
        for (int b = 0; b < 8; ++b)
            #pragma unroll
            for (int c = 0; c < 4; ++c) acc[a][b][c] = 0.f;

    const int wid = tid >> 5, lane = tid & 31;
    const int wm = wid >> 2, wn = wid & 3;
    int g_cnt = (Np - wn * 64) / 16;
    if (g_cnt < 0) g_cnt = 0;
    if (g_cnt > 4) g_cnt = 4;

    const int t = lane >> 3, idx = lane & 7;
    const uint32_t aoff = (uint32_t)(((idx + (t & 1) * 8) * SA + (t >> 1) * 8) * 2);
    const uint32_t boff = (uint32_t)(((idx + (t >> 1) * 8) * SW + (t & 1) * 8) * 2);

    const int chunks = (Kp + KC - 1) / KC;
    { int kc0 = min(KC, Kp); stage_w(sb, 0, w, Kp, Np, 0, kc0, tid); CP_COMMIT(); }

    for (int c = 0; c < chunks; ++c) {
        CP_WAIT0();
        __syncthreads();
        if (c + 1 < chunks) {
            int kcn = min(KC, Kp - (c + 1) * KC);
            stage_w(sb, (c + 1) & 1, w, Kp, Np, (c + 1) * KC, kcn, tid);
            CP_COMMIT();
        }
        const int kc = min(KC, Kp - c * KC);
        if (g_cnt > 0) {
            const uint32_t wbase = sb + WOFF + (uint32_t)(c & 1) * WSLOT;
            for (int ks = 0; ks < kc; ks += 16) {
                const int kk = c * KC + ks;
                uint32_t ah[2][4], al[2][4];
                #pragma unroll
                for (int ma = 0; ma < 2; ++ma) {
                    uint32_t ra = (uint32_t)(((wm * 32 + ma * 16) * SA + kk) * 2) + aoff;
                    ldm_x4(ah[ma], sb + AHI_OFF + ra);
                    ldm_x4(al[ma], sb + ALO_OFF + ra);
                }
                for (int g = 0; g < g_cnt; ++g) {
                    const int n0 = wn * 64 + g * 16;
                    uint32_t rb = (uint32_t)((n0 * SW + ks) * 2) + boff;
                    uint32_t bh[4];
                    ldm_x4(bh, wbase + rb);
                    #pragma unroll
                    for (int ma = 0; ma < 2; ++ma) {
                        mma16816(acc[ma][2 * g],     ah[ma], bh[0], bh[1]);
                        mma16816(acc[ma][2 * g],     al[ma], bh[0], bh[1]);
                        mma16816(acc[ma][2 * g + 1], ah[ma], bh[2], bh[3]);
                        mma16816(acc[ma][2 * g + 1], al[ma], bh[2], bh[3]);
                    }
                }
            }
        }
    }
    __syncthreads();
}

// relu(acc+bias) -> fp16 hi/lo, in place into A smem
__device__ __forceinline__ void epi_hidden(char* sm, const float* __restrict__ bias,
                                           int tid, float (&acc)[2][8][4])
{
    const int wid = tid >> 5, lane = tid & 31;
    const int wm = wid >> 2, wn = wid & 3;
    const int gid = lane >> 2, tig = lane & 3;
    #pragma unroll
    for (int ma = 0; ma < 2; ++ma)
        #pragma unroll
        for (int na = 0; na < 8; ++na) {
            const float* A4 = acc[ma][na];
            int r = wm * 32 + ma * 16 + gid;
            int c = wn * 64 + na * 8 + 2 * tig;
            float b0 = __ldg(bias + c), b1 = __ldg(bias + c + 1);
            uint32_t lo0, lo1;
            uint32_t hi0 = pack_split(fmaxf(A4[0] + b0, 0.f), fmaxf(A4[1] + b1, 0.f), lo0);
            uint32_t hi1 = pack_split(fmaxf(A4[2] + b0, 0.f), fmaxf(A4[3] + b1, 0.f), lo1);
            *(uint32_t*)(sm + AHI_OFF + (r * SA + c) * 2)       = hi0;
            *(uint32_t*)(sm + ALO_OFF + (r * SA + c) * 2)       = lo0;
            *(uint32_t*)(sm + AHI_OFF + ((r + 8) * SA + c) * 2) = hi1;
            *(uint32_t*)(sm + ALO_OFF + ((r + 8) * SA + c) * 2) = lo1;
        }
    __syncthreads();
}

__device__ __forceinline__ void epi_final(const float* __restrict__ bias, int out_dim,
    float* __restrict__ out, int out_ld, int out_off, int row0, int tid,
    float (&acc)[2][8][4])
{
    const int wid = tid >> 5, lane = tid & 31;
    const int wm = wid >> 2, wn = wid & 3;
    const int gid = lane >> 2, tig = lane & 3;
    #pragma unroll
    for (int ma = 0; ma < 2; ++ma)
        for (int na = 0; na < 8; ++na) {
            int c = wn * 64 + na * 8 + 2 * tig;
            if (c >= out_dim) continue;
            const float* A4 = acc[ma][na];
            int r = row0 + wm * 32 + ma * 16 + gid;
            float b0 = __ldg(bias + c);
            out[(size_t)r * out_ld + out_off + c]       = A4[0] + b0;
            out[(size_t)(r + 8) * out_ld + out_off + c] = A4[2] + b0;
            if (c + 1 < out_dim) {
                float b1 = __ldg(bias + c + 1);
                out[(size_t)r * out_ld + out_off + c + 1]       = A4[1] + b1;
                out[(size_t)(r + 8) * out_ld + out_off + c + 1] = A4[3] + b1;
            }
        }
}

// ======================= fused 3-layer MLP kernel ============================
__global__ void __launch_bounds__(NTHR, 1) mlp_mma(
    const float* __restrict__ in, int in_ld, int in_off, int K1t, int K1p,
    const uint16_t* __restrict__ w1, const float* __restrict__ b1,
    const uint16_t* __restrict__ w2, const float* __restrict__ b2,
    const uint16_t* __restrict__ w3, const float* __restrict__ b3,
    int Np3, int out_dim,
    float* __restrict__ out, int out_ld, int out_off)
{
    extern __shared__ char sm[];
    const uint32_t sb = smem_u32(sm);
    const int tid = threadIdx.x;
    const int row0 = blockIdx.x * ROWS;

    // stage layer-1 A (fp32 -> fp16 hi/lo), zero-padded to K1p
    for (int i = tid; i < ROWS * K1p; i += NTHR) {
        int r = i / K1p, k = i - r * K1p;
        float v = (k < K1t) ? in[(size_t)(row0 + r) * in_ld + in_off + k] : 0.f;
        __half h = __float2half_rn(v);
        __half l = __float2half_rn(v - __half2float(h));
        *(uint16_t*)(sm + AHI_OFF + (r * SA + k) * 2) = __half_as_ushort(h);
        *(uint16_t*)(sm + ALO_OFF + (r * SA + k) * 2) = __half_as_ushort(l);
    }
    __syncthreads();

    float acc[2][8][4];
    lay(sm, sb, w1, K1p, 256, tid, acc);
    epi_hidden(sm, b1, tid, acc);
    lay(sm, sb, w2, 256, 256, tid, acc);
    epi_hidden(sm, b2, tid, acc);
    lay(sm, sb, w3, 256, Np3, tid, acc);
    epi_final(b3, out_dim, out, out_ld, out_off, row0, tid, acc);
}

// ======================= Koopman recurrence (fp32, proven) ===================
union F2U { float2 f; unsigned long long u; };
__device__ __forceinline__ float2 ffma2(float2 a, float2 b, float2 c) {
    F2U A, Bv, C; A.f = a; Bv.f = b; C.f = c;
    asm("fma.rn.f32x2 %0, %1, %2, %0;" : "+l"(C.u) : "l"(A.u), "l"(Bv.u));
    return C.f;
}

__global__ void __launch_bounds__(256, 2) koopman_kernel(
    const float* __restrict__ zk, const float* __restrict__ u,
    const float* __restrict__ A, const float* __restrict__ Bw,
    float* __restrict__ zpred)
{
    extern __shared__ float smem[];
    float* As = smem;
    float* z0 = As + 16384;
    float* z1 = z0 + 4224;
    float* bw = z1 + 4224;
    float* us = bw + 512;

    const int tid  = threadIdx.x;
    const int row0 = blockIdx.x * 32;

    for (int i = tid; i < 16384; i += 256) {
        int o = i & 127, k = i >> 7;
        As[k * 128 + o] = A[o * 128 + k];
    }
    for (int i = tid; i < 512; i += 256) {
        int o = i & 127, j = i >> 7;
        bw[j * 128 + o] = Bw[o * 4 + j];
    }
    for (int i = tid; i < 4096; i += 256) {
        int r = i >> 7, k = i & 127;
        z0[r * 132 + k] = zk[(size_t)(row0 + r) * 128 + k];
    }
    const int oc = (tid & 63) * 2;
    const int rg = tid >> 6;
    __syncthreads();

    for (int s = 0; s < 64; ++s) {
        if (tid < 128) {
            int r = tid >> 2, j = tid & 3;
            us[r * 4 + j] = u[((size_t)(row0 + r) * 64 + s) * 4 + j];
        }
        __syncthreads();
        const float* zc = (s & 1) ? z1 : z0;
        float*       zn = (s & 1) ? z0 : z1;

        float2 acc[8];
        #pragma unroll
        for (int r = 0; r < 8; ++r) acc[r] = make_float2(0.f, 0.f);

        #pragma unroll
        for (int j = 0; j < 4; ++j) {
            float2 bv = *(const float2*)&bw[j * 128 + oc];
            #pragma unroll
            for (int r = 0; r < 8; ++r) {
                float uv = us[(rg * 8 + r) * 4 + j];
                acc[r] = ffma2(bv, make_float2(uv, uv), acc[r]);
            }
        }
        for (int k = 0; k < 128; ++k) {
            float2 av = *(const float2*)&As[k * 128 + oc];
            #pragma unroll
            for (int r = 0; r < 8; ++r) {
                float zv = zc[(rg * 8 + r) * 132 + k];
                acc[r] = ffma2(av, make_float2(zv, zv), acc[r]);
            }
        }
        #pragma unroll
        for (int r = 0; r < 8; ++r) {
            int rr = rg * 8 + r;
            *(float2*)&zn[rr * 132 + oc] = acc[r];
            *(float2*)&zpred[(((size_t)(row0 + rr)) * 64 + s) * 128 + oc] = acc[r];
        }
        __syncthreads();
    }
}

// ======================= host launcher ======================================
extern "C" void kernel_launch(void* const* d_in, const int* in_sizes, int n_in,
                              void* d_out, int out_size) {
    (void)in_sizes; (void)n_in; (void)out_size;
    const float* x_k   = (const float*)d_in[0];
    const float* u_seq = (const float*)d_in[1];
    const float* xnext = (const float*)d_in[2];
    WP wp;
    wp.w[0]  = (const float*)d_in[3];  wp.w[1]  = (const float*)d_in[5];
    wp.w[2]  = (const float*)d_in[7];  wp.w[3]  = (const float*)d_in[9];
    wp.w[4]  = (const float*)d_in[11]; wp.w[5]  = (const float*)d_in[13];
    wp.w[6]  = (const float*)d_in[15]; wp.w[7]  = (const float*)d_in[17];
    wp.w[8]  = (const float*)d_in[19]; wp.w[9]  = (const float*)d_in[21];
    wp.w[10] = (const float*)d_in[23]; wp.w[11] = (const float*)d_in[25];
    const float* Bv[12] = {
        (const float*)d_in[4],  (const float*)d_in[6],  (const float*)d_in[8],
        (const float*)d_in[10], (const float*)d_in[12], (const float*)d_in[14],
        (const float*)d_in[16], (const float*)d_in[18], (const float*)d_in[20],
        (const float*)d_in[22], (const float*)d_in[24], (const float*)d_in[26]
    };
    const float* A_w = (const float*)d_in[27];
    const float* B_w = (const float*)d_in[28];

    float* out = (float*)d_out;
    const size_t B = 8192, M = 64;
    float* o1 = out;                 // x_k_hat        [B,12]
    float* o2 = o1 + B * 12;         // x_target_hat   [B,M,12]
    float* o3 = o2 + B * M * 12;     // z_pred_seq     [B,M,128]
    float* o4 = o3 + B * M * 128;    // x_pred_hat     [B,M,12]
    float* o5 = o4 + B * M * 12;     // z_target_seq   [B,M,128]

    void *wqp, *zkp;
    cudaGetSymbolAddress(&wqp, g_w);
    cudaGetSymbolAddress(&zkp, g_zk);
    __half* wq = (__half*)wqp;
    float* zk = (float*)zkp;

    static const int T[12] = {0, 4096, 69632, 77824, 81920, 147456,
                              172032, 180224, 245760, 249856, 274432, 339968};

    const int KOOP_SMEM = (16384 + 2 * 4224 + 512 + 128) * (int)sizeof(float);
    cudaFuncSetAttribute(mlp_mma, cudaFuncAttributeMaxDynamicSharedMemorySize, SMEM_TOT);
    cudaFuncSetAttribute(koopman_kernel, cudaFuncAttributeMaxDynamicSharedMemorySize, KOOP_SMEM);

    const int GBM = (int)(B * M / ROWS);  // 4096
    const int GB  = (int)(B / ROWS);      // 64

    #define RUN(grid, inp, ild, ioff, K1t, K1p, net, Np3, od, op, old, ooff) \
        mlp_mma<<<grid, NTHR, SMEM_TOT>>>(inp, ild, ioff, K1t, K1p, \
            (const uint16_t*)(wq + T[(net)*3]),   Bv[(net)*3], \
            (const uint16_t*)(wq + T[(net)*3+1]), Bv[(net)*3+1], \
            (const uint16_t*)(wq + T[(net)*3+2]), Bv[(net)*3+2], \
            Np3, od, op, old, ooff)

    // 1: weight prep; 2,3: encode x_k -> zk; 4: GBM encode (ncu capture slot)
    wprep_all<<<dim3(256, 12), 256>>>(wp, wq);
    RUN(GB,  x_k,   12, 0, 3,  16, 0, 32, 32, zk, 128, 0);
    RUN(GB,  x_k,   12, 3, 9,  16, 1, 96, 96, zk, 128, 32);
    RUN(GBM, xnext, 12, 0, 3,  16, 0, 32, 32, o5, 128, 0);
    RUN(GBM, xnext, 12, 3, 9,  16, 1, 96, 96, o5, 128, 32);
    koopman_kernel<<<(int)(B / 32), 256, KOOP_SMEM>>>(zk, u_seq, A_w, B_w, o3);
    // decode z_k -> o1
    RUN(GB,  zk, 128, 0,  32, 32, 2, 16, 3, o1, 12, 0);
    RUN(GB,  zk, 128, 32, 96, 96, 3, 16, 9, o1, 12, 3);
    // decode z_target -> o2
    RUN(GBM, o5, 128, 0,  32, 32, 2, 16, 3, o2, 12, 0);
    RUN(GBM, o5, 128, 32, 96, 96, 3, 16, 9, o2, 12, 3);
    // decode z_pred -> o4
    RUN(GBM, o3, 128, 0,  32, 32, 2, 16, 3, o4, 12, 0);
    RUN(GBM, o3, 128, 32, 96, 96, 3, 16, 9, o4, 12, 3);
    #undef RUN
}

// round 10
// speedup vs baseline: 9.1502x; 1.1717x over previous
#include <cuda_runtime.h>
#include <cuda_fp16.h>
#include <cstdint>
#include <cstddef>

// ======================= scratch (no allocations allowed) ====================
__device__ float g_zk[8192 * 128];
__device__ __align__(16) __half g_w[345088];

// ======================= smem layout (bytes) ================================
// A: 64 rows x 264 fp16 (stride 264), hi then lo.        2 x 33792
// W: double-buffered chunks, 256 rows x 40 fp16 stride.  2 x 20480
#define NTHR 256
#define ROWS 64
#define SA 264
#define SW 40
#define KC 32
#define AHI_OFF 0
#define ALO_OFF 33792
#define WOFF    67584
#define WSLOT   20480
#define SMEM_TOT 108544

__device__ __forceinline__ uint32_t smem_u32(const void* p) {
    uint32_t a;
    asm("{ .reg .u64 t; cvta.to.shared.u64 t, %1; cvt.u32.u64 %0, t; }"
        : "=r"(a) : "l"(p));
    return a;
}
__device__ __forceinline__ void ldm_x4(uint32_t* r, uint32_t addr) {
    asm volatile("ldmatrix.sync.aligned.m8n8.x4.shared.b16 {%0,%1,%2,%3}, [%4];"
                 : "=r"(r[0]), "=r"(r[1]), "=r"(r[2]), "=r"(r[3]) : "r"(addr));
}
__device__ __forceinline__ void mma16816(float* c, const uint32_t* a,
                                         uint32_t b0, uint32_t b1) {
    asm volatile("mma.sync.aligned.m16n8k16.row.col.f32.f16.f16.f32 "
                 "{%0,%1,%2,%3}, {%4,%5,%6,%7}, {%8,%9}, {%0,%1,%2,%3};"
                 : "+f"(c[0]), "+f"(c[1]), "+f"(c[2]), "+f"(c[3])
                 : "r"(a[0]), "r"(a[1]), "r"(a[2]), "r"(a[3]), "r"(b0), "r"(b1));
}
__device__ __forceinline__ void cpa16(uint32_t dst, const void* src) {
    asm volatile("cp.async.cg.shared.global [%0], [%1], 16;" :: "r"(dst), "l"(src));
}
#define CP_COMMIT() asm volatile("cp.async.commit_group;" ::: "memory")
#define CP_WAIT0()  asm volatile("cp.async.wait_group 0;" ::: "memory")

__device__ __forceinline__ uint32_t pack_split(float v0, float v1, uint32_t& lo) {
    __half h0 = __float2half_rn(v0), h1 = __float2half_rn(v1);
    float r0 = v0 - __half2float(h0), r1 = v1 - __half2float(h1);
    __half l0 = __float2half_rn(r0), l1 = __float2half_rn(r1);
    lo = (uint32_t)__half_as_ushort(l0) | ((uint32_t)__half_as_ushort(l1) << 16);
    return (uint32_t)__half_as_ushort(h0) | ((uint32_t)__half_as_ushort(h1) << 16);
}

// ======================= fused weight prep (ONE launch) ======================
// {off, Nt, Kt, Np, Kp} per layer, 4 networks x 3 layers
__device__ const int dT[12][5] = {
    {0,      256, 3,   256, 16},  {4096,   256, 256, 256, 256}, {69632,  32,  256, 32,  256},
    {77824,  256, 9,   256, 16},  {81920,  256, 256, 256, 256}, {147456, 96,  256, 96,  256},
    {172032, 256, 32,  256, 32},  {180224, 256, 256, 256, 256}, {245760, 3,   256, 16,  256},
    {249856, 256, 96,  256, 96},  {274432, 256, 256, 256, 256}, {339968, 9,   256, 16,  256}
};
struct WP { const float* w[12]; };

__global__ void wprep_all(WP p, __half* __restrict__ wq) {
    const int net = blockIdx.y;
    const int off = dT[net][0], Nt = dT[net][1], Kt = dT[net][2];
    const int Np = dT[net][3], Kp = dT[net][4];
    const float* W = p.w[net];
    for (int i = blockIdx.x * 256 + threadIdx.x; i < Np * Kp; i += gridDim.x * 256) {
        int n = i / Kp, k = i - n * Kp;
        float w = (n < Nt && k < Kt) ? W[n * Kt + k] : 0.f;
        wq[off + i] = __float2half_rn(w);
    }
}

// ======================= weight chunk staging (cp.async) =====================
__device__ __forceinline__ void stage_w(uint32_t sb, int slot,
    const uint16_t* __restrict__ w, int Kp, int Np, int k0, int kc, int tid)
{
    const int spr = kc >> 3;          // 16B segments per row (2 or 4)
    const int per = Np * spr;
    const uint32_t base = sb + WOFF + slot * WSLOT;
    for (int i = tid; i < per; i += NTHR) {
        int row = i / spr, seg = i - row * spr;
        cpa16(base + row * (SW * 2) + seg * 16, w + row * Kp + k0 + seg * 8);
    }
}

// ======================= one GEMM layer (HMMA, fp16 2-term split) ============
// warps: wm=wid>>2 (2 row groups of 32), wn=wid&3 (4 col groups of 64)
__device__ __forceinline__ void lay(char* sm, uint32_t sb,
    const uint16_t* __restrict__ w, int Kp, int Np, int tid, float (&acc)[2][8][4])
{
    #pragma unroll
    for (int a = 0; a < 2; ++a)
        #pragma unroll
        for (int b = 0; b < 8; ++b)
            #pragma unroll
            for (int c = 0; c < 4; ++c) acc[a][b][c] = 0.f;

    const int wid = tid >> 5, lane = tid & 31;
    const int wm = wid >> 2, wn = wid & 3;
    int g_cnt = (Np - wn * 64) / 16;
    if (g_cnt < 0) g_cnt = 0;
    if (g_cnt > 4) g_cnt = 4;

    const int t = lane >> 3, idx = lane & 7;
    const uint32_t aoff = (uint32_t)(((idx + (t & 1) * 8) * SA + (t >> 1) * 8) * 2);
    const uint32_t boff = (uint32_t)(((idx + (t >> 1) * 8) * SW + (t & 1) * 8) * 2);

    const int chunks = (Kp + KC - 1) / KC;
    { int kc0 = min(KC, Kp); stage_w(sb, 0, w, Kp, Np, 0, kc0, tid); CP_COMMIT(); }

    for (int c = 0; c < chunks; ++c) {
        CP_WAIT0();
        __syncthreads();
        if (c + 1 < chunks) {
            int kcn = min(KC, Kp - (c + 1) * KC);
            stage_w(sb, (c + 1) & 1, w, Kp, Np, (c + 1) * KC, kcn, tid);
            CP_COMMIT();
        }
        const int kc = min(KC, Kp - c * KC);
        if (g_cnt > 0) {
            const uint32_t wbase = sb + WOFF + (uint32_t)(c & 1) * WSLOT;
            for (int ks = 0; ks < kc; ks += 16) {
                const int kk = c * KC + ks;
                uint32_t ah[2][4], al[2][4];
                #pragma unroll
                for (int ma = 0; ma < 2; ++ma) {
                    uint32_t ra = (uint32_t)(((wm * 32 + ma * 16) * SA + kk) * 2) + aoff;
                    ldm_x4(ah[ma], sb + AHI_OFF + ra);
                    ldm_x4(al[ma], sb + ALO_OFF + ra);
                }
                for (int g = 0; g < g_cnt; ++g) {
                    const int n0 = wn * 64 + g * 16;
                    uint32_t rb = (uint32_t)((n0 * SW + ks) * 2) + boff;
                    uint32_t bh[4];
                    ldm_x4(bh, wbase + rb);
                    #pragma unroll
                    for (int ma = 0; ma < 2; ++ma) {
                        mma16816(acc[ma][2 * g],     ah[ma], bh[0], bh[1]);
                        mma16816(acc[ma][2 * g],     al[ma], bh[0], bh[1]);
                        mma16816(acc[ma][2 * g + 1], ah[ma], bh[2], bh[3]);
                        mma16816(acc[ma][2 * g + 1], al[ma], bh[2], bh[3]);
                    }
                }
            }
        }
    }
    __syncthreads();
}

// relu(acc+bias) -> fp16 hi/lo, in place into A smem
__device__ __forceinline__ void epi_hidden(char* sm, const float* __restrict__ bias,
                                           int tid, float (&acc)[2][8][4])
{
    const int wid = tid >> 5, lane = tid & 31;
    const int wm = wid >> 2, wn = wid & 3;
    const int gid = lane >> 2, tig = lane & 3;
    #pragma unroll
    for (int ma = 0; ma < 2; ++ma)
        #pragma unroll
        for (int na = 0; na < 8; ++na) {
            const float* A4 = acc[ma][na];
            int r = wm * 32 + ma * 16 + gid;
            int c = wn * 64 + na * 8 + 2 * tig;
            float b0 = __ldg(bias + c), b1 = __ldg(bias + c + 1);
            uint32_t lo0, lo1;
            uint32_t hi0 = pack_split(fmaxf(A4[0] + b0, 0.f), fmaxf(A4[1] + b1, 0.f), lo0);
            uint32_t hi1 = pack_split(fmaxf(A4[2] + b0, 0.f), fmaxf(A4[3] + b1, 0.f), lo1);
            *(uint32_t*)(sm + AHI_OFF + (r * SA + c) * 2)       = hi0;
            *(uint32_t*)(sm + ALO_OFF + (r * SA + c) * 2)       = lo0;
            *(uint32_t*)(sm + AHI_OFF + ((r + 8) * SA + c) * 2) = hi1;
            *(uint32_t*)(sm + ALO_OFF + ((r + 8) * SA + c) * 2) = lo1;
        }
    __syncthreads();
}

__device__ __forceinline__ void epi_final(const float* __restrict__ bias, int out_dim,
    float* __restrict__ out, int out_ld, int out_off, int row0, int tid,
    float (&acc)[2][8][4])
{
    const int wid = tid >> 5, lane = tid & 31;
    const int wm = wid >> 2, wn = wid & 3;
    const int gid = lane >> 2, tig = lane & 3;
    #pragma unroll
    for (int ma = 0; ma < 2; ++ma)
        for (int na = 0; na < 8; ++na) {
            int c = wn * 64 + na * 8 + 2 * tig;
            if (c >= out_dim) continue;
            const float* A4 = acc[ma][na];
            int r = row0 + wm * 32 + ma * 16 + gid;
            float b0 = __ldg(bias + c);
            out[(size_t)r * out_ld + out_off + c]       = A4[0] + b0;
            out[(size_t)(r + 8) * out_ld + out_off + c] = A4[2] + b0;
            if (c + 1 < out_dim) {
                float b1 = __ldg(bias + c + 1);
                out[(size_t)r * out_ld + out_off + c + 1]       = A4[1] + b1;
                out[(size_t)(r + 8) * out_ld + out_off + c + 1] = A4[3] + b1;
            }
        }
}

// ======================= fused 3-layer MLP kernel ============================
__global__ void __launch_bounds__(NTHR, 2) mlp_mma(
    const float* __restrict__ in, int in_ld, int in_off, int K1t, int K1p,
    const uint16_t* __restrict__ w1, const float* __restrict__ b1,
    const uint16_t* __restrict__ w2, const float* __restrict__ b2,
    const uint16_t* __restrict__ w3, const float* __restrict__ b3,
    int Np3, int out_dim,
    float* __restrict__ out, int out_ld, int out_off)
{
    extern __shared__ char sm[];
    const uint32_t sb = smem_u32(sm);
    const int tid = threadIdx.x;
    const int row0 = blockIdx.x * ROWS;

    // stage layer-1 A (fp32 -> fp16 hi/lo), zero-padded to K1p
    for (int i = tid; i < ROWS * K1p; i += NTHR) {
        int r = i / K1p, k = i - r * K1p;
        float v = (k < K1t) ? in[(size_t)(row0 + r) * in_ld + in_off + k] : 0.f;
        __half h = __float2half_rn(v);
        __half l = __float2half_rn(v - __half2float(h));
        *(uint16_t*)(sm + AHI_OFF + (r * SA + k) * 2) = __half_as_ushort(h);
        *(uint16_t*)(sm + ALO_OFF + (r * SA + k) * 2) = __half_as_ushort(l);
    }
    __syncthreads();

    float acc[2][8][4];
    lay(sm, sb, w1, K1p, 256, tid, acc);
    epi_hidden(sm, b1, tid, acc);
    lay(sm, sb, w2, 256, 256, tid, acc);
    epi_hidden(sm, b2, tid, acc);
    lay(sm, sb, w3, 256, Np3, tid, acc);
    epi_final(b3, out_dim, out, out_ld, out_off, row0, tid, acc);
}

// ======================= Koopman recurrence (fp32, proven) ===================
union F2U { float2 f; unsigned long long u; };
__device__ __forceinline__ float2 ffma2(float2 a, float2 b, float2 c) {
    F2U A, Bv, C; A.f = a; Bv.f = b; C.f = c;
    asm("fma.rn.f32x2 %0, %1, %2, %0;" : "+l"(C.u) : "l"(A.u), "l"(Bv.u));
    return C.f;
}

__global__ void __launch_bounds__(256, 2) koopman_kernel(
    const float* __restrict__ zk, const float* __restrict__ u,
    const float* __restrict__ A, const float* __restrict__ Bw,
    float* __restrict__ zpred)
{
    extern __shared__ float smem[];
    float* As = smem;
    float* z0 = As + 16384;
    float* z1 = z0 + 4224;
    float* bw = z1 + 4224;
    float* us = bw + 512;

    const int tid  = threadIdx.x;
    const int row0 = blockIdx.x * 32;

    for (int i = tid; i < 16384; i += 256) {
        int o = i & 127, k = i >> 7;
        As[k * 128 + o] = A[o * 128 + k];
    }
    for (int i = tid; i < 512; i += 256) {
        int o = i & 127, j = i >> 7;
        bw[j * 128 + o] = Bw[o * 4 + j];
    }
    for (int i = tid; i < 4096; i += 256) {
        int r = i >> 7, k = i & 127;
        z0[r * 132 + k] = zk[(size_t)(row0 + r) * 128 + k];
    }
    const int oc = (tid & 63) * 2;
    const int rg = tid >> 6;
    __syncthreads();

    for (int s = 0; s < 64; ++s) {
        if (tid < 128) {
            int r = tid >> 2, j = tid & 3;
            us[r * 4 + j] = u[((size_t)(row0 + r) * 64 + s) * 4 + j];
        }
        __syncthreads();
        const float* zc = (s & 1) ? z1 : z0;
        float*       zn = (s & 1) ? z0 : z1;

        float2 acc[8];
        #pragma unroll
        for (int r = 0; r < 8; ++r) acc[r] = make_float2(0.f, 0.f);

        #pragma unroll
        for (int j = 0; j < 4; ++j) {
            float2 bv = *(const float2*)&bw[j * 128 + oc];
            #pragma unroll
            for (int r = 0; r < 8; ++r) {
                float uv = us[(rg * 8 + r) * 4 + j];
                acc[r] = ffma2(bv, make_float2(uv, uv), acc[r]);
            }
        }
        for (int k = 0; k < 128; ++k) {
            float2 av = *(const float2*)&As[k * 128 + oc];
            #pragma unroll
            for (int r = 0; r < 8; ++r) {
                float zv = zc[(rg * 8 + r) * 132 + k];
                acc[r] = ffma2(av, make_float2(zv, zv), acc[r]);
            }
        }
        #pragma unroll
        for (int r = 0; r < 8; ++r) {
            int rr = rg * 8 + r;
            *(float2*)&zn[rr * 132 + oc] = acc[r];
            *(float2*)&zpred[(((size_t)(row0 + rr)) * 64 + s) * 128 + oc] = acc[r];
        }
        __syncthreads();
    }
}

// ======================= host launcher ======================================
extern "C" void kernel_launch(void* const* d_in, const int* in_sizes, int n_in,
                              void* d_out, int out_size) {
    (void)in_sizes; (void)n_in; (void)out_size;
    const float* x_k   = (const float*)d_in[0];
    const float* u_seq = (const float*)d_in[1];
    const float* xnext = (const float*)d_in[2];
    WP wp;
    wp.w[0]  = (const float*)d_in[3];  wp.w[1]  = (const float*)d_in[5];
    wp.w[2]  = (const float*)d_in[7];  wp.w[3]  = (const float*)d_in[9];
    wp.w[4]  = (const float*)d_in[11]; wp.w[5]  = (const float*)d_in[13];
    wp.w[6]  = (const float*)d_in[15]; wp.w[7]  = (const float*)d_in[17];
    wp.w[8]  = (const float*)d_in[19]; wp.w[9]  = (const float*)d_in[21];
    wp.w[10] = (const float*)d_in[23]; wp.w[11] = (const float*)d_in[25];
    const float* Bv[12] = {
        (const float*)d_in[4],  (const float*)d_in[6],  (const float*)d_in[8],
        (const float*)d_in[10], (const float*)d_in[12], (const float*)d_in[14],
        (const float*)d_in[16], (const float*)d_in[18], (const float*)d_in[20],
        (const float*)d_in[22], (const float*)d_in[24], (const float*)d_in[26]
    };
    const float* A_w = (const float*)d_in[27];
    const float* B_w = (const float*)d_in[28];

    float* out = (float*)d_out;
    const size_t B = 8192, M = 64;
    float* o1 = out;                 // x_k_hat        [B,12]
    float* o2 = o1 + B * 12;         // x_target_hat   [B,M,12]
    float* o3 = o2 + B * M * 12;     // z_pred_seq     [B,M,128]
    float* o4 = o3 + B * M * 128;    // x_pred_hat     [B,M,12]
    float* o5 = o4 + B * M * 12;     // z_target_seq   [B,M,128]

    void *wqp, *zkp;
    cudaGetSymbolAddress(&wqp, g_w);
    cudaGetSymbolAddress(&zkp, g_zk);
    __half* wq = (__half*)wqp;
    float* zk = (float*)zkp;

    static const int T[12] = {0, 4096, 69632, 77824, 81920, 147456,
                              172032, 180224, 245760, 249856, 274432, 339968};

    const int KOOP_SMEM = (16384 + 2 * 4224 + 512 + 128) * (int)sizeof(float);
    cudaFuncSetAttribute(mlp_mma, cudaFuncAttributeMaxDynamicSharedMemorySize, SMEM_TOT);
    cudaFuncSetAttribute(koopman_kernel, cudaFuncAttributeMaxDynamicSharedMemorySize, KOOP_SMEM);

    const int GBM = (int)(B * M / ROWS);  // 8192
    const int GB  = (int)(B / ROWS);      // 128

    #define RUN(grid, inp, ild, ioff, K1t, K1p, net, Np3, od, op, old, ooff) \
        mlp_mma<<<grid, NTHR, SMEM_TOT>>>(inp, ild, ioff, K1t, K1p, \
            (const uint16_t*)(wq + T[(net)*3]),   Bv[(net)*3], \
            (const uint16_t*)(wq + T[(net)*3+1]), Bv[(net)*3+1], \
            (const uint16_t*)(wq + T[(net)*3+2]), Bv[(net)*3+2], \
            Np3, od, op, old, ooff)

    // 1: weight prep; 2,3: encode x_k -> zk; 4: GBM encode (ncu capture slot)
    wprep_all<<<dim3(256, 12), 256>>>(wp, wq);
    RUN(GB,  x_k,   12, 0, 3,  16, 0, 32, 32, zk, 128, 0);
    RUN(GB,  x_k,   12, 3, 9,  16, 1, 96, 96, zk, 128, 32);
    RUN(GBM, xnext, 12, 0, 3,  16, 0, 32, 32, o5, 128, 0);
    RUN(GBM, xnext, 12, 3, 9,  16, 1, 96, 96, o5, 128, 32);
    koopman_kernel<<<(int)(B / 32), 256, KOOP_SMEM>>>(zk, u_seq, A_w, B_w, o3);
    // decode z_k -> o1
    RUN(GB,  zk, 128, 0,  32, 32, 2, 16, 3, o1, 12, 0);
    RUN(GB,  zk, 128, 32, 96, 96, 3, 16, 9, o1, 12, 3);
    // decode z_target -> o2
    RUN(GBM, o5, 128, 0,  32, 32, 2, 16, 3, o2, 12, 0);
    RUN(GBM, o5, 128, 32, 96, 96, 3, 16, 9, o2, 12, 3);
    // decode z_pred -> o4
    RUN(GBM, o3, 128, 0,  32, 32, 2, 16, 3, o4, 12, 0);
    RUN(GBM, o3, 128, 32, 96, 96, 3, 16, 9, o4, 12, 3);
    #undef RUN
}